// round 10
// baseline (speedup 1.0000x reference)
#include <cuda_runtime.h>
#include <cuda_bf16.h>
#include <cstdint>
#include <cstdio>

#define E_DIM 1024
#define H_DIM 1024
#define VOC   32000
#define T_STEPS 64
#define NBLK  128          // persistent LSTM blocks
#define NGATE 4096

// -------- device scratch (no allocs allowed) --------
__device__ float g_X[T_STEPS * E_DIM];              // inputs per step
__device__ float g_hpub[(T_STEPS + 1) * H_DIM];     // fresh h row per step
__device__ float g_Xg[T_STEPS * NGATE];             // permuted gate inputs + bias
__device__ unsigned int g_cnt;                      // single barrier counter

__device__ __forceinline__ float sigmoidf_(float x) { return 1.f / (1.f + __expf(-x)); }
__device__ __forceinline__ float tanhf_(float x) {
    return __fdividef(2.f, 1.f + __expf(-2.f * x)) - 1.f;
}

// ---- packed f32x2 helpers ----
__device__ __forceinline__ void fma2(unsigned long long& d,
                                     unsigned long long a, unsigned long long b) {
    asm("fma.rn.f32x2 %0, %1, %2, %0;" : "+l"(d) : "l"(a), "l"(b));
}
__device__ __forceinline__ float sum2(unsigned long long v) {
    float lo, hi;
    asm("mov.b64 {%0, %1}, %2;" : "=f"(lo), "=f"(hi) : "l"(v));
    return lo + hi;
}
__device__ __forceinline__ void ld2u64(const void* p, unsigned long long& a,
                                       unsigned long long& b) {
    asm("ld.global.v2.u64 {%0, %1}, [%2];" : "=l"(a), "=l"(b) : "l"(p));
}
__device__ __forceinline__ void ld2u64_cg(const void* p, unsigned long long& a,
                                          unsigned long long& b) {
    asm("ld.global.cg.v2.u64 {%0, %1}, [%2];" : "=l"(a), "=l"(b) : "l"(p));
}

// =====================================================================
// K0: build X, init h row 0 + counter
// =====================================================================
__global__ void prep_kernel(const int* __restrict__ captions,
                            const float* __restrict__ features,
                            const float* __restrict__ etab) {
    int t = blockIdx.x;
    const float* src = (t == 0) ? features : (etab + (size_t)captions[t - 1] * E_DIM);
    for (int k = threadIdx.x; k < E_DIM; k += blockDim.x)
        g_X[t * E_DIM + k] = src[k];
    if (t == 0) {
        for (int k = threadIdx.x; k < H_DIM; k += blockDim.x) g_hpub[k] = 0.f;
        if (threadIdx.x == 0) g_cnt = 0u;
    }
}

// ======================= shared MMA machinery ========================
#define FC_M    128
#define FC_NCH  16

#define FCO_AF32(b) ((b) * 32768)
#define FCO_AHI     65536
#define FCO_ALO     81920
#define FCO_BHI     98304
#define FCO_BLO     106496
#define FC_SMEM     114688      // 112 KB -> 2 CTAs/SM

#define SWZ(x) ((x) ^ (((x) >> 3) & 0x70))

__device__ __forceinline__ uint32_t smem_u32(const void* p) {
    uint32_t a;
    asm("{ .reg .u64 t; cvta.to.shared.u64 t, %1; cvt.u32.u64 %0, t; }" : "=r"(a) : "l"(p));
    return a;
}

__device__ __forceinline__ void split2(float2 a, uint32_t& hi, uint32_t& lo) {
    __nv_bfloat162 h = __float22bfloat162_rn(a);
    float2 f = __bfloat1622float2(h);
    __nv_bfloat162 l2 = __float22bfloat162_rn(make_float2(a.x - f.x, a.y - f.y));
    hi = *reinterpret_cast<uint32_t*>(&h);
    lo = *reinterpret_cast<uint32_t*>(&l2);
}

#define CP16(dst, src) \
    asm volatile("cp.async.cg.shared.global [%0], [%1], 16;" :: "r"(dst), "l"(src) : "memory")
#define CP_COMMIT() asm volatile("cp.async.commit_group;" ::: "memory")
#define CP_WAIT(n)  asm volatile("cp.async.wait_group %0;" :: "n"(n) : "memory")

#define LDM_X4(r, a)                                                          \
    asm volatile("ldmatrix.sync.aligned.m8n8.x4.shared.b16 {%0,%1,%2,%3}, [%4];" \
        : "=r"((r)[0]), "=r"((r)[1]), "=r"((r)[2]), "=r"((r)[3]) : "r"(a))

#define MMA16816(d, a, b0, b1)                                                \
    asm volatile("mma.sync.aligned.m16n8k16.row.col.f32.bf16.bf16.f32 "       \
        "{%0,%1,%2,%3},{%4,%5,%6,%7},{%8,%9},{%0,%1,%2,%3};"                  \
        : "+f"((d)[0]), "+f"((d)[1]), "+f"((d)[2]), "+f"((d)[3])              \
        : "r"((a)[0]), "r"((a)[1]), "r"((a)[2]), "r"((a)[3]),                 \
          "r"(b0), "r"(b1))

// Shared main body: A = aW rows [vbase..vbase+128), B = bSrc rows (64 x 1024,
// row stride 1024 floats). Accumulates acc[2][8][4]. Used by both GEMM kernels.
#define MMA_BODY(aW, bRowPtr)                                                  \
    auto issue = [&](int c) {                                                  \
        const uint32_t dbase = sb + FCO_AF32(c & 1);                           \
        _Pragma("unroll")                                                      \
        for (int p = 0; p < 16; p++) {                                         \
            int idx = tid + p * 128;                                           \
            int row = idx >> 4, seg = idx & 15;                                \
            const char* src = (const char*)((aW) + (size_t)(vbase + row) * E_DIM + c * 64) \
                              + seg * 16;                                      \
            CP16(dbase + (uint32_t)(row * 256 + seg * 16), src);               \
        }                                                                      \
        CP_COMMIT();                                                           \
    };                                                                         \
    issue(0);                                                                  \
    issue(1);                                                                  \
    for (int c = 0; c < FC_NCH; c++) {                                         \
        if (c < FC_NCH - 1) { CP_WAIT(1); } else { CP_WAIT(0); }               \
        __syncthreads();                                                       \
        {                                                                      \
            const char* af = smem + FCO_AF32(c & 1);                           \
            _Pragma("unroll")                                                  \
            for (int p = 0; p < 32; p++) {                                     \
                int fidx = tid + p * 128;                                      \
                int row = fidx >> 5, kp = fidx & 31;                           \
                float2 a = *(const float2*)(af + row * 256 + kp * 8);          \
                uint32_t hi, lo; split2(a, hi, lo);                            \
                uint32_t off = SWZ((uint32_t)(row * 128 + kp * 4));            \
                *(uint32_t*)(smem + FCO_AHI + off) = hi;                       \
                *(uint32_t*)(smem + FCO_ALO + off) = lo;                       \
            }                                                                  \
        }                                                                      \
        {                                                                      \
            _Pragma("unroll")                                                  \
            for (int p = 0; p < 16; p++) {                                     \
                int fidx = tid + p * 128;                                      \
                int row = fidx >> 5, kp = fidx & 31;                           \
                float2 a = *(const float2*)((bRowPtr(row)) + c * 64 + kp * 2); \
                uint32_t hi, lo; split2(a, hi, lo);                            \
                uint32_t off = SWZ((uint32_t)(row * 128 + kp * 4));            \
                *(uint32_t*)(smem + FCO_BHI + off) = hi;                       \
                *(uint32_t*)(smem + FCO_BLO + off) = lo;                       \
            }                                                                  \
        }                                                                      \
        __syncthreads();                                                       \
        if (c + 2 < FC_NCH) issue(c + 2);                                      \
        const uint32_t sAhi = sb + FCO_AHI, sAlo = sb + FCO_ALO;               \
        const uint32_t sBhi = sb + FCO_BHI, sBlo = sb + FCO_BLO;               \
        _Pragma("unroll")                                                      \
        for (int ks = 0; ks < 4; ks++) {                                       \
            const uint32_t akb = (uint32_t)(ks * 32) + a_kh;                   \
            const uint32_t bkb = (uint32_t)(ks * 32) + b_kh;                   \
            uint32_t ah[2][4], al[2][4];                                       \
            _Pragma("unroll")                                                  \
            for (int mt = 0; mt < 2; mt++) {                                   \
                uint32_t off = a_roff + (uint32_t)(mt * 16 * 128) + (akb ^ a_xor); \
                LDM_X4(ah[mt], sAhi + off);                                    \
                LDM_X4(al[mt], sAlo + off);                                    \
            }                                                                  \
            uint32_t bh[4][4], bl[4][4];                                       \
            _Pragma("unroll")                                                  \
            for (int bp = 0; bp < 4; bp++) {                                   \
                uint32_t n = (uint32_t)(bp * 16 + b_rsub);                     \
                uint32_t off = n * 128 + (bkb ^ b_xor);                        \
                LDM_X4(bh[bp], sBhi + off);                                    \
                LDM_X4(bl[bp], sBlo + off);                                    \
            }                                                                  \
            _Pragma("unroll")                                                  \
            for (int mt = 0; mt < 2; mt++)                                     \
                _Pragma("unroll")                                              \
                for (int nt = 0; nt < 8; nt++) {                               \
                    const int bp = nt >> 1, sel = (nt & 1) * 2;                \
                    MMA16816(acc[mt][nt], ah[mt], bh[bp][sel], bh[bp][sel + 1]); \
                    MMA16816(acc[mt][nt], al[mt], bh[bp][sel], bh[bp][sel + 1]); \
                    MMA16816(acc[mt][nt], ah[mt], bl[bp][sel], bl[bp][sel + 1]); \
                }                                                              \
        }                                                                      \
    }

#define MMA_PREAMBLE                                                           \
    extern __shared__ __align__(1024) char smem[];                             \
    const uint32_t sb = smem_u32(smem);                                        \
    const int tid  = threadIdx.x;                                              \
    const int wid  = tid >> 5;                                                 \
    const int lane = tid & 31;                                                 \
    const int vbase = blockIdx.x * FC_M;                                       \
    const int m0 = wid * 32;                                                   \
    const int a_row  = m0 + (lane & 15);                                       \
    const uint32_t a_roff = (uint32_t)a_row * 128;                             \
    const uint32_t a_xor  = (uint32_t)(a_row & 7) << 4;                        \
    const uint32_t a_kh   = (uint32_t)(lane >> 4) * 16;                        \
    const int b_rsub = (lane & 7) + ((lane >> 4) & 1) * 8;                     \
    const uint32_t b_xor = (uint32_t)(lane & 7) << 4;                          \
    const uint32_t b_kh  = (uint32_t)((lane >> 3) & 1) * 16;                   \
    float acc[2][8][4];                                                        \
    _Pragma("unroll")                                                          \
    for (int mt = 0; mt < 2; mt++)                                             \
        _Pragma("unroll")                                                      \
        for (int nt = 0; nt < 8; nt++)                                         \
            _Pragma("unroll")                                                  \
            for (int q = 0; q < 4; q++) acc[mt][nt][q] = 0.f;

// =====================================================================
// K1: Xg = X @ W_ih^T + bias  (32 CTAs), permuted epilogue:
//   g_Xg[t*4096 + blk*32 + gate*8 + j]  for gate-row r = gate*1024 + blk*8 + j
// =====================================================================
__device__ __forceinline__ int xg_dst(int r, int t) {
    return t * NGATE + (((r & 1023) >> 3) << 5) + ((r >> 10) << 3) + (r & 7);
}

__global__ void __launch_bounds__(128, 2)
xg_mma_kernel(const float* __restrict__ Wih,
              const float* __restrict__ bih, const float* __restrict__ bhh) {
    MMA_PREAMBLE
#define XG_BROW(row) (g_X + (row) * E_DIM)
    MMA_BODY(Wih, XG_BROW)
#undef XG_BROW

    const int g  = lane >> 2;
    const int t4 = lane & 3;
#pragma unroll
    for (int mt = 0; mt < 2; mt++) {
        int r0 = vbase + m0 + mt * 16 + g;
        float bv0 = bih[r0] + bhh[r0];
        float bv8 = bih[r0 + 8] + bhh[r0 + 8];
#pragma unroll
        for (int nt = 0; nt < 8; nt++) {
            int t0 = nt * 8 + t4 * 2;
            g_Xg[xg_dst(r0,     t0)]     = acc[mt][nt][0] + bv0;
            g_Xg[xg_dst(r0,     t0 + 1)] = acc[mt][nt][1] + bv0;
            g_Xg[xg_dst(r0 + 8, t0)]     = acc[mt][nt][2] + bv8;
            g_Xg[xg_dst(r0 + 8, t0 + 1)] = acc[mt][nt][3] + bv8;
        }
    }
}

// =====================================================================
// K2: persistent LSTM recurrence only (Phase A removed).
// Block b owns h indices [8b, 8b+8). Thread: j=tid&7, c=tid>>3.
// =====================================================================
__global__ void __launch_bounds__(512, 1)
lstm_kernel(const float* __restrict__ Whh) {
    __shared__ float partA[16][32];        // [warp][g*8+j]

    const int tid = threadIdx.x;
    const int w   = tid >> 5;
    const int l   = tid & 31;
    const int j   = tid & 7;
    const int c   = tid >> 3;     // 0..63
    const int b   = blockIdx.x;
    const int jg  = b * 8 + j;

    float creg = 0.f;             // cell state (tid < 8)

    unsigned long long wreg2[4][8];
#pragma unroll
    for (int g = 0; g < 4; g++) {
        const char* p = (const char*)(Whh + (size_t)(g * H_DIM + jg) * H_DIM + c * 16);
#pragma unroll
        for (int q = 0; q < 4; q++)
            ld2u64(p + q * 16, wreg2[g][2*q], wreg2[g][2*q+1]);
    }
    __syncthreads();

    for (int t = 0; t < T_STEPS; t++) {
        // warp 0: issue the (Xg+bias) load early — consumed after sync1
        float xgv = 0.f;
        if (tid < 32)
            xgv = __ldcg(&g_Xg[t * NGATE + b * 32 + tid]);

        // h row t guaranteed ready by previous step's barrier
        unsigned long long hv2[8];
        {
            const char* hp = (const char*)(g_hpub + t * H_DIM + c * 16);
#pragma unroll
            for (int q = 0; q < 4; q++)
                ld2u64_cg(hp + q * 16, hv2[2*q], hv2[2*q+1]);
        }
        float part[4];
#pragma unroll
        for (int g = 0; g < 4; g++) {
            unsigned long long acc = 0ull;
#pragma unroll
            for (int i = 0; i < 8; i++) fma2(acc, wreg2[g][i], hv2[i]);
            part[g] = sum2(acc);
        }
#pragma unroll
        for (int g = 0; g < 4; g++) {
            part[g] += __shfl_xor_sync(0xffffffffu, part[g], 8);
            part[g] += __shfl_xor_sync(0xffffffffu, part[g], 16);
        }
        if (l < 8) {
#pragma unroll
            for (int g = 0; g < 4; g++) partA[w][g * 8 + l] = part[g];
        }
        __syncthreads();                          // sync1

        if (tid < 32) {
            float s = xgv;
#pragma unroll
            for (int ww = 0; ww < 16; ww++) s += partA[ww][tid];

            const int jj = tid & 7;
            float sf = __shfl_sync(0xffffffffu, s, jj + 8);
            float sg = __shfl_sync(0xffffffffu, s, jj + 16);
            float so = __shfl_sync(0xffffffffu, s, jj + 24);

            if (tid < 8) {
                float ii = sigmoidf_(s);
                float ff = sigmoidf_(sf);
                float gg = tanhf_(sg);
                float oo = sigmoidf_(so);
                float cc = ff * creg + ii * gg;
                creg = cc;
                float hn = oo * tanhf_(cc);

                float vv[8];
#pragma unroll
                for (int i = 0; i < 8; i++)
                    vv[i] = __shfl_sync(0x000000FFu, hn, i, 8);
                if (tid == 0) {
                    float4* dst = (float4*)(g_hpub + (t + 1) * H_DIM + b * 8);
                    dst[0] = make_float4(vv[0], vv[1], vv[2], vv[3]);
                    dst[1] = make_float4(vv[4], vv[5], vv[6], vv[7]);
                    asm volatile("red.release.gpu.global.add.u32 [%0], 1;"
                                 :: "l"(&g_cnt) : "memory");
                }
            }
            if (tid == 0) {
                const unsigned int target = (unsigned)NBLK * (unsigned)(t + 1);
                unsigned int v;
                do {
                    asm volatile("ld.acquire.gpu.u32 %0, [%1];"
                                 : "=r"(v) : "l"(&g_cnt) : "memory");
                } while (v < target);
            }
        }
        __syncthreads();                          // sync_final
    }
}

// =====================================================================
// K3: fc GEMM (proven round-5 core). B tile reads g_hpub rows 1..64.
// =====================================================================
__global__ void __launch_bounds__(128, 2)
fc_mma_kernel(const float* __restrict__ fcW, const float* __restrict__ fcb,
              float* __restrict__ out) {
    MMA_PREAMBLE
#define FC_BROW(row) (g_hpub + ((row) + 1) * H_DIM)
    MMA_BODY(fcW, FC_BROW)
#undef FC_BROW

    const int g  = lane >> 2;
    const int t4 = lane & 3;
#pragma unroll
    for (int mt = 0; mt < 2; mt++) {
        int v0 = vbase + m0 + mt * 16 + g;
        float bv0 = fcb[v0];
        float bv8 = fcb[v0 + 8];
#pragma unroll
        for (int nt = 0; nt < 8; nt++) {
            int t0 = nt * 8 + t4 * 2;
            out[(size_t)t0 * VOC + v0]           = acc[mt][nt][0] + bv0;
            out[(size_t)(t0 + 1) * VOC + v0]     = acc[mt][nt][1] + bv0;
            out[(size_t)t0 * VOC + v0 + 8]       = acc[mt][nt][2] + bv8;
            out[(size_t)(t0 + 1) * VOC + v0 + 8] = acc[mt][nt][3] + bv8;
        }
    }
}

// =====================================================================
// launch
// =====================================================================
extern "C" void kernel_launch(void* const* d_in, const int* in_sizes, int n_in,
                              void* d_out, int out_size) {
    const int*   captions = (const int*)  d_in[0];
    const float* features = (const float*)d_in[1];
    const float* etab     = (const float*)d_in[2];
    const float* W_ih     = (const float*)d_in[3];
    const float* W_hh     = (const float*)d_in[4];
    const float* b_ih     = (const float*)d_in[5];
    const float* b_hh     = (const float*)d_in[6];
    const float* fc_W     = (const float*)d_in[7];
    const float* fc_b     = (const float*)d_in[8];
    float* out = (float*)d_out;

    cudaFuncSetAttribute(xg_mma_kernel,
                         cudaFuncAttributeMaxDynamicSharedMemorySize, FC_SMEM);
    cudaFuncSetAttribute(fc_mma_kernel,
                         cudaFuncAttributeMaxDynamicSharedMemorySize, FC_SMEM);

    prep_kernel<<<T_STEPS, 256>>>(captions, features, etab);
    xg_mma_kernel<<<NGATE / FC_M, 128, FC_SMEM>>>(W_ih, b_ih, b_hh);
    lstm_kernel<<<NBLK, 512>>>(W_hh);
    fc_mma_kernel<<<VOC / FC_M, 128, FC_SMEM>>>(fc_W, fc_b, out);
}

// round 11
// speedup vs baseline: 1.0086x; 1.0086x over previous
#include <cuda_runtime.h>
#include <cuda_bf16.h>
#include <cstdint>
#include <cstdio>

#define E_DIM 1024
#define H_DIM 1024
#define VOC   32000
#define T_STEPS 64
#define NBLK  128
#define NGATE 4096

// -------- device scratch --------
__device__ float g_X[T_STEPS * E_DIM];
__device__ float g_hpub[(T_STEPS + 1) * H_DIM];
__device__ float g_Xg[T_STEPS * NGATE];
__device__ unsigned int g_cnt;

__device__ __forceinline__ float sigmoidf_(float x) { return 1.f / (1.f + __expf(-x)); }
__device__ __forceinline__ float tanhf_(float x) {
    return __fdividef(2.f, 1.f + __expf(-2.f * x)) - 1.f;
}

// ---- packed f32x2 helpers ----
__device__ __forceinline__ void fma2(unsigned long long& d,
                                     unsigned long long a, unsigned long long b) {
    asm("fma.rn.f32x2 %0, %1, %2, %0;" : "+l"(d) : "l"(a), "l"(b));
}
__device__ __forceinline__ float sum2(unsigned long long v) {
    float lo, hi;
    asm("mov.b64 {%0, %1}, %2;" : "=f"(lo), "=f"(hi) : "l"(v));
    return lo + hi;
}
__device__ __forceinline__ void ld2u64(const void* p, unsigned long long& a,
                                       unsigned long long& b) {
    asm("ld.global.v2.u64 {%0, %1}, [%2];" : "=l"(a), "=l"(b) : "l"(p));
}
__device__ __forceinline__ void ld2u64_cg(const void* p, unsigned long long& a,
                                          unsigned long long& b) {
    asm("ld.global.cg.v2.u64 {%0, %1}, [%2];" : "=l"(a), "=l"(b) : "l"(p));
}

// =====================================================================
// K0: build X, init h row 0 + counter
// =====================================================================
__global__ void prep_kernel(const int* __restrict__ captions,
                            const float* __restrict__ features,
                            const float* __restrict__ etab) {
    int t = blockIdx.x;
    const float* src = (t == 0) ? features : (etab + (size_t)captions[t - 1] * E_DIM);
    for (int k = threadIdx.x; k < E_DIM; k += blockDim.x)
        g_X[t * E_DIM + k] = src[k];
    if (t == 0) {
        for (int k = threadIdx.x; k < H_DIM; k += blockDim.x) g_hpub[k] = 0.f;
        if (threadIdx.x == 0) g_cnt = 0u;
    }
}

// ======================= shared GEMM helpers =========================
#define FC_M    128
#define FC_NCH  16

#define FCO_AF32(b) ((b) * 32768)
#define FCO_AHI     65536
#define FCO_ALO     81920
#define FCO_BHI     98304
#define FCO_BLO     106496
#define FC_SMEM     114688      // 112 KB -> 2 CTAs/SM

#define SWZ(x) ((x) ^ (((x) >> 3) & 0x70))

__device__ __forceinline__ uint32_t smem_u32(const void* p) {
    uint32_t a;
    asm("{ .reg .u64 t; cvta.to.shared.u64 t, %1; cvt.u32.u64 %0, t; }" : "=r"(a) : "l"(p));
    return a;
}

__device__ __forceinline__ void split2(float2 a, uint32_t& hi, uint32_t& lo) {
    __nv_bfloat162 h = __float22bfloat162_rn(a);
    float2 f = __bfloat1622float2(h);
    __nv_bfloat162 l2 = __float22bfloat162_rn(make_float2(a.x - f.x, a.y - f.y));
    hi = *reinterpret_cast<uint32_t*>(&h);
    lo = *reinterpret_cast<uint32_t*>(&l2);
}

#define CP16(dst, src) \
    asm volatile("cp.async.cg.shared.global [%0], [%1], 16;" :: "r"(dst), "l"(src) : "memory")
#define CP_COMMIT() asm volatile("cp.async.commit_group;" ::: "memory")
#define CP_WAIT(n)  asm volatile("cp.async.wait_group %0;" :: "n"(n) : "memory")

#define LDM_X4(r, a)                                                          \
    asm volatile("ldmatrix.sync.aligned.m8n8.x4.shared.b16 {%0,%1,%2,%3}, [%4];" \
        : "=r"((r)[0]), "=r"((r)[1]), "=r"((r)[2]), "=r"((r)[3]) : "r"(a))

#define MMA16816(d, a, b0, b1)                                                \
    asm volatile("mma.sync.aligned.m16n8k16.row.col.f32.bf16.bf16.f32 "       \
        "{%0,%1,%2,%3},{%4,%5,%6,%7},{%8,%9},{%0,%1,%2,%3};"                  \
        : "+f"((d)[0]), "+f"((d)[1]), "+f"((d)[2]), "+f"((d)[3])              \
        : "r"((a)[0]), "r"((a)[1]), "r"((a)[2]), "r"((a)[3]),                 \
          "r"(b0), "r"(b1))

// =====================================================================
// K1: Xg = X @ W_ih^T + bias  (32 CTAs), permuted epilogue.
// Explicit R5-style body (A fused convert, B from g_X).
// =====================================================================
__device__ __forceinline__ int xg_dst(int r, int t) {
    return t * NGATE + (((r & 1023) >> 3) << 5) + ((r >> 10) << 3) + (r & 7);
}

__global__ void __launch_bounds__(128, 2)
xg_mma_kernel(const float* __restrict__ Wih,
              const float* __restrict__ bih, const float* __restrict__ bhh) {
    extern __shared__ __align__(1024) char smem[];
    const uint32_t sb = smem_u32(smem);

    const int tid  = threadIdx.x;
    const int wid  = tid >> 5;
    const int lane = tid & 31;
    const int vbase = blockIdx.x * FC_M;
    const int m0 = wid * 32;

    const int a_row  = m0 + (lane & 15);
    const uint32_t a_roff = (uint32_t)a_row * 128;
    const uint32_t a_xor  = (uint32_t)(a_row & 7) << 4;
    const uint32_t a_kh   = (uint32_t)(lane >> 4) * 16;
    const int b_rsub = (lane & 7) + ((lane >> 4) & 1) * 8;
    const uint32_t b_xor = (uint32_t)(lane & 7) << 4;
    const uint32_t b_kh  = (uint32_t)((lane >> 3) & 1) * 16;

    float acc[2][8][4];
#pragma unroll
    for (int mt = 0; mt < 2; mt++)
#pragma unroll
        for (int nt = 0; nt < 8; nt++)
#pragma unroll
            for (int q = 0; q < 4; q++) acc[mt][nt][q] = 0.f;

    auto issue = [&](int c) {
        const uint32_t dbase = sb + FCO_AF32(c & 1);
#pragma unroll
        for (int p = 0; p < 16; p++) {
            int idx = tid + p * 128;
            int row = idx >> 4, seg = idx & 15;
            const char* src = (const char*)(Wih + (size_t)(vbase + row) * E_DIM + c * 64)
                              + seg * 16;
            CP16(dbase + (uint32_t)(row * 256 + seg * 16), src);
        }
        CP_COMMIT();
    };

    issue(0);
    issue(1);

    for (int c = 0; c < FC_NCH; c++) {
        if (c < FC_NCH - 1) { CP_WAIT(1); } else { CP_WAIT(0); }
        __syncthreads();

        {
            const char* af = smem + FCO_AF32(c & 1);
#pragma unroll
            for (int p = 0; p < 32; p++) {
                int fidx = tid + p * 128;
                int row = fidx >> 5, kp = fidx & 31;
                float2 a = *(const float2*)(af + row * 256 + kp * 8);
                uint32_t hi, lo; split2(a, hi, lo);
                uint32_t off = SWZ((uint32_t)(row * 128 + kp * 4));
                *(uint32_t*)(smem + FCO_AHI + off) = hi;
                *(uint32_t*)(smem + FCO_ALO + off) = lo;
            }
        }
        {
#pragma unroll
            for (int p = 0; p < 16; p++) {
                int fidx = tid + p * 128;
                int row = fidx >> 5, kp = fidx & 31;
                float2 a = *(const float2*)(g_X + row * E_DIM + c * 64 + kp * 2);
                uint32_t hi, lo; split2(a, hi, lo);
                uint32_t off = SWZ((uint32_t)(row * 128 + kp * 4));
                *(uint32_t*)(smem + FCO_BHI + off) = hi;
                *(uint32_t*)(smem + FCO_BLO + off) = lo;
            }
        }
        __syncthreads();

        if (c + 2 < FC_NCH) issue(c + 2);

        const uint32_t sAhi = sb + FCO_AHI, sAlo = sb + FCO_ALO;
        const uint32_t sBhi = sb + FCO_BHI, sBlo = sb + FCO_BLO;
#pragma unroll
        for (int ks = 0; ks < 4; ks++) {
            const uint32_t akb = (uint32_t)(ks * 32) + a_kh;
            const uint32_t bkb = (uint32_t)(ks * 32) + b_kh;

            uint32_t ah[2][4], al[2][4];
#pragma unroll
            for (int mt = 0; mt < 2; mt++) {
                uint32_t off = a_roff + (uint32_t)(mt * 16 * 128) + (akb ^ a_xor);
                LDM_X4(ah[mt], sAhi + off);
                LDM_X4(al[mt], sAlo + off);
            }
            uint32_t bh[4][4], bl[4][4];
#pragma unroll
            for (int bp = 0; bp < 4; bp++) {
                uint32_t n = (uint32_t)(bp * 16 + b_rsub);
                uint32_t off = n * 128 + (bkb ^ b_xor);
                LDM_X4(bh[bp], sBhi + off);
                LDM_X4(bl[bp], sBlo + off);
            }
#pragma unroll
            for (int mt = 0; mt < 2; mt++)
#pragma unroll
                for (int nt = 0; nt < 8; nt++) {
                    const int bp = nt >> 1, sel = (nt & 1) * 2;
                    MMA16816(acc[mt][nt], ah[mt], bh[bp][sel], bh[bp][sel + 1]);
                    MMA16816(acc[mt][nt], al[mt], bh[bp][sel], bh[bp][sel + 1]);
                    MMA16816(acc[mt][nt], ah[mt], bl[bp][sel], bl[bp][sel + 1]);
                }
        }
    }

    const int g  = lane >> 2;
    const int t4 = lane & 3;
#pragma unroll
    for (int mt = 0; mt < 2; mt++) {
        int r0 = vbase + m0 + mt * 16 + g;
        float bv0 = bih[r0] + bhh[r0];
        float bv8 = bih[r0 + 8] + bhh[r0 + 8];
#pragma unroll
        for (int nt = 0; nt < 8; nt++) {
            int t0 = nt * 8 + t4 * 2;
            g_Xg[xg_dst(r0,     t0)]     = acc[mt][nt][0] + bv0;
            g_Xg[xg_dst(r0,     t0 + 1)] = acc[mt][nt][1] + bv0;
            g_Xg[xg_dst(r0 + 8, t0)]     = acc[mt][nt][2] + bv8;
            g_Xg[xg_dst(r0 + 8, t0 + 1)] = acc[mt][nt][3] + bv8;
        }
    }
}

// =====================================================================
// K2: persistent LSTM recurrence. Overlapped poll: warp1 polls while
// warp0 runs the publish tail. Lanes 0-7 store hn directly (no gather).
// =====================================================================
__global__ void __launch_bounds__(512, 1)
lstm_kernel(const float* __restrict__ Whh) {
    __shared__ float partA[16][32];

    const int tid = threadIdx.x;
    const int w   = tid >> 5;
    const int l   = tid & 31;
    const int j   = tid & 7;
    const int c   = tid >> 3;
    const int b   = blockIdx.x;
    const int jg  = b * 8 + j;

    float creg = 0.f;

    unsigned long long wreg2[4][8];
#pragma unroll
    for (int g = 0; g < 4; g++) {
        const char* p = (const char*)(Whh + (size_t)(g * H_DIM + jg) * H_DIM + c * 16);
#pragma unroll
        for (int q = 0; q < 4; q++)
            ld2u64(p + q * 16, wreg2[g][2*q], wreg2[g][2*q+1]);
    }
    __syncthreads();

    for (int t = 0; t < T_STEPS; t++) {
        float xgv = 0.f;
        if (tid < 32)
            xgv = __ldcg(&g_Xg[t * NGATE + b * 32 + tid]);

        unsigned long long hv2[8];
        {
            const char* hp = (const char*)(g_hpub + t * H_DIM + c * 16);
#pragma unroll
            for (int q = 0; q < 4; q++)
                ld2u64_cg(hp + q * 16, hv2[2*q], hv2[2*q+1]);
        }
        float part[4];
#pragma unroll
        for (int g = 0; g < 4; g++) {
            unsigned long long acc = 0ull;
#pragma unroll
            for (int i = 0; i < 8; i++) fma2(acc, wreg2[g][i], hv2[i]);
            part[g] = sum2(acc);
        }
#pragma unroll
        for (int g = 0; g < 4; g++) {
            part[g] += __shfl_xor_sync(0xffffffffu, part[g], 8);
            part[g] += __shfl_xor_sync(0xffffffffu, part[g], 16);
        }
        if (l < 8) {
#pragma unroll
            for (int g = 0; g < 4; g++) partA[w][g * 8 + l] = part[g];
        }
        __syncthreads();                          // sync1

        if (tid < 32) {
            // warp 0: final reduce + activations + publish
            float s = xgv;
#pragma unroll
            for (int ww = 0; ww < 16; ww++) s += partA[ww][tid];

            const int jj = tid & 7;
            float sf = __shfl_sync(0xffffffffu, s, jj + 8);
            float sg = __shfl_sync(0xffffffffu, s, jj + 16);
            float so = __shfl_sync(0xffffffffu, s, jj + 24);

            if (tid < 8) {
                float ii = sigmoidf_(s);
                float ff = sigmoidf_(sf);
                float gg = tanhf_(sg);
                float oo = sigmoidf_(so);
                float cc = ff * creg + ii * gg;
                creg = cc;
                float hn = oo * tanhf_(cc);
                // direct coalesced 32B publish (one sector)
                g_hpub[(t + 1) * H_DIM + b * 8 + tid] = hn;
            }
            __syncwarp();
            if (tid == 0) {
                // release covers lanes 0-7's stores (ordered via syncwarp)
                asm volatile("red.release.gpu.global.add.u32 [%0], 1;"
                             :: "l"(&g_cnt) : "memory");
            }
        } else if (tid == 32 && t + 1 < T_STEPS) {
            // warp 1: poll concurrently with warp 0's tail
            const unsigned int target = (unsigned)NBLK * (unsigned)(t + 1);
            unsigned int v;
            do {
                asm volatile("ld.acquire.gpu.u32 %0, [%1];"
                             : "=r"(v) : "l"(&g_cnt) : "memory");
            } while (v < target);
        }
        __syncthreads();                          // sync_final
    }
}

// =====================================================================
// K3: fc GEMM — explicit R5 body (A fused convert, B from g_hpub).
// =====================================================================
__global__ void __launch_bounds__(128, 2)
fc_mma_kernel(const float* __restrict__ fcW, const float* __restrict__ fcb,
              float* __restrict__ out) {
    extern __shared__ __align__(1024) char smem[];
    const uint32_t sb = smem_u32(smem);

    const int tid  = threadIdx.x;
    const int wid  = tid >> 5;
    const int lane = tid & 31;
    const int vbase = blockIdx.x * FC_M;
    const int m0 = wid * 32;

    const int a_row  = m0 + (lane & 15);
    const uint32_t a_roff = (uint32_t)a_row * 128;
    const uint32_t a_xor  = (uint32_t)(a_row & 7) << 4;
    const uint32_t a_kh   = (uint32_t)(lane >> 4) * 16;
    const int b_rsub = (lane & 7) + ((lane >> 4) & 1) * 8;
    const uint32_t b_xor = (uint32_t)(lane & 7) << 4;
    const uint32_t b_kh  = (uint32_t)((lane >> 3) & 1) * 16;

    float acc[2][8][4];
#pragma unroll
    for (int mt = 0; mt < 2; mt++)
#pragma unroll
        for (int nt = 0; nt < 8; nt++)
#pragma unroll
            for (int q = 0; q < 4; q++) acc[mt][nt][q] = 0.f;

    auto issue = [&](int c) {
        const uint32_t dbase = sb + FCO_AF32(c & 1);
#pragma unroll
        for (int p = 0; p < 16; p++) {
            int idx = tid + p * 128;
            int row = idx >> 4, seg = idx & 15;
            const char* src = (const char*)(fcW + (size_t)(vbase + row) * E_DIM + c * 64)
                              + seg * 16;
            CP16(dbase + (uint32_t)(row * 256 + seg * 16), src);
        }
        CP_COMMIT();
    };

    issue(0);
    issue(1);

    for (int c = 0; c < FC_NCH; c++) {
        if (c < FC_NCH - 1) { CP_WAIT(1); } else { CP_WAIT(0); }
        __syncthreads();

        {
            const char* af = smem + FCO_AF32(c & 1);
#pragma unroll
            for (int p = 0; p < 32; p++) {
                int fidx = tid + p * 128;
                int row = fidx >> 5, kp = fidx & 31;
                float2 a = *(const float2*)(af + row * 256 + kp * 8);
                uint32_t hi, lo; split2(a, hi, lo);
                uint32_t off = SWZ((uint32_t)(row * 128 + kp * 4));
                *(uint32_t*)(smem + FCO_AHI + off) = hi;
                *(uint32_t*)(smem + FCO_ALO + off) = lo;
            }
        }
        {
#pragma unroll
            for (int p = 0; p < 16; p++) {
                int fidx = tid + p * 128;
                int row = fidx >> 5, kp = fidx & 31;
                float2 a = *(const float2*)(g_hpub + (row + 1) * H_DIM + c * 64 + kp * 2);
                uint32_t hi, lo; split2(a, hi, lo);
                uint32_t off = SWZ((uint32_t)(row * 128 + kp * 4));
                *(uint32_t*)(smem + FCO_BHI + off) = hi;
                *(uint32_t*)(smem + FCO_BLO + off) = lo;
            }
        }
        __syncthreads();

        if (c + 2 < FC_NCH) issue(c + 2);

        const uint32_t sAhi = sb + FCO_AHI, sAlo = sb + FCO_ALO;
        const uint32_t sBhi = sb + FCO_BHI, sBlo = sb + FCO_BLO;
#pragma unroll
        for (int ks = 0; ks < 4; ks++) {
            const uint32_t akb = (uint32_t)(ks * 32) + a_kh;
            const uint32_t bkb = (uint32_t)(ks * 32) + b_kh;

            uint32_t ah[2][4], al[2][4];
#pragma unroll
            for (int mt = 0; mt < 2; mt++) {
                uint32_t off = a_roff + (uint32_t)(mt * 16 * 128) + (akb ^ a_xor);
                LDM_X4(ah[mt], sAhi + off);
                LDM_X4(al[mt], sAlo + off);
            }
            uint32_t bh[4][4], bl[4][4];
#pragma unroll
            for (int bp = 0; bp < 4; bp++) {
                uint32_t n = (uint32_t)(bp * 16 + b_rsub);
                uint32_t off = n * 128 + (bkb ^ b_xor);
                LDM_X4(bh[bp], sBhi + off);
                LDM_X4(bl[bp], sBlo + off);
            }
#pragma unroll
            for (int mt = 0; mt < 2; mt++)
#pragma unroll
                for (int nt = 0; nt < 8; nt++) {
                    const int bp = nt >> 1, sel = (nt & 1) * 2;
                    MMA16816(acc[mt][nt], ah[mt], bh[bp][sel], bh[bp][sel + 1]);
                    MMA16816(acc[mt][nt], al[mt], bh[bp][sel], bh[bp][sel + 1]);
                    MMA16816(acc[mt][nt], ah[mt], bl[bp][sel], bl[bp][sel + 1]);
                }
        }
    }

    const int g  = lane >> 2;
    const int t4 = lane & 3;
#pragma unroll
    for (int mt = 0; mt < 2; mt++) {
        int v0 = vbase + m0 + mt * 16 + g;
        float bv0 = fcb[v0];
        float bv8 = fcb[v0 + 8];
#pragma unroll
        for (int nt = 0; nt < 8; nt++) {
            int t0 = nt * 8 + t4 * 2;
            out[(size_t)t0 * VOC + v0]           = acc[mt][nt][0] + bv0;
            out[(size_t)(t0 + 1) * VOC + v0]     = acc[mt][nt][1] + bv0;
            out[(size_t)t0 * VOC + v0 + 8]       = acc[mt][nt][2] + bv8;
            out[(size_t)(t0 + 1) * VOC + v0 + 8] = acc[mt][nt][3] + bv8;
        }
    }
}

// =====================================================================
// launch
// =====================================================================
extern "C" void kernel_launch(void* const* d_in, const int* in_sizes, int n_in,
                              void* d_out, int out_size) {
    const int*   captions = (const int*)  d_in[0];
    const float* features = (const float*)d_in[1];
    const float* etab     = (const float*)d_in[2];
    const float* W_ih     = (const float*)d_in[3];
    const float* W_hh     = (const float*)d_in[4];
    const float* b_ih     = (const float*)d_in[5];
    const float* b_hh     = (const float*)d_in[6];
    const float* fc_W     = (const float*)d_in[7];
    const float* fc_b     = (const float*)d_in[8];
    float* out = (float*)d_out;

    cudaFuncSetAttribute(xg_mma_kernel,
                         cudaFuncAttributeMaxDynamicSharedMemorySize, FC_SMEM);
    cudaFuncSetAttribute(fc_mma_kernel,
                         cudaFuncAttributeMaxDynamicSharedMemorySize, FC_SMEM);

    prep_kernel<<<T_STEPS, 256>>>(captions, features, etab);
    xg_mma_kernel<<<NGATE / FC_M, 128, FC_SMEM>>>(W_ih, b_ih, b_hh);
    lstm_kernel<<<NBLK, 512>>>(W_hh);
    fc_mma_kernel<<<VOC / FC_M, 128, FC_SMEM>>>(fc_W, fc_b, out);
}